// round 13
// baseline (speedup 1.0000x reference)
#include <cuda_runtime.h>
#include <math.h>
#include <limits.h>

#define Nn 30000
#define Ee 400000
#define C1n 15000
#define E2n 100000
#define C2n 7500
#define Bn 16

#define T1S 168   // T1 row stride (162 used)
#define K1 162    // 150 w1b + 6 b1b + 6 root1
#define T2S 864   // T2 row stride
#define K2 864    // 800 w2b + 32 b2b + 32 root2

typedef unsigned long long ull;

// ---------------- zero-init block (single memset 0) ---------------------------
struct ZBlk {
    int   degD1[Nn];
    int   degD2[C1n], cntc1[C1n];
    float possum[C1n * 3];
    float gsum[Bn * 64];
    float gcnt[Bn];
    float maxabs;
};
// ---------------- 0xff-init block (single memset 0xff) ------------------------
struct FBlk {
    float xp[C1n * 32];      // 0xffffffff sentinel (loses to all atomicMaxFloat)
    float x3[C2n * 64];
    int   batchp[C1n];       // -1
    int   batch2[C2n];       // -1
};
__device__ ZBlk gz;
__device__ FBlk gf;

// ---------------- uninitialized scratch ----------------------------------------
__device__ int g_offD1[Nn + 1], g_curD1[Nn];
__device__ int g_offD2[C1n + 1], g_curD2[C1n];
__device__ __align__(16) float4 g_e4[Ee];          // {ea0,ea1,ea2, src-bits} dst-sorted
__device__ int g_csrD2s[E2n];                      // src ids dst-sorted
__device__ __align__(16) float g_T1[(size_t)Nn * T1S];
__device__ __align__(16) float g_T2[(size_t)C1n * T2S];

__device__ __forceinline__ void atomicMaxFloat(float* addr, float val) {
    if (val >= 0.f) atomicMax((int*)addr, __float_as_int(val));
    else            atomicMin((unsigned int*)addr, __float_as_uint(val));
}
__device__ __forceinline__ float elu1(float v) { return v > 0.f ? v : expm1f(v); }
__device__ __forceinline__ float fixneg(float v) { return (v > -3e38f) ? v : 0.f; }

// ---------------- K1: histograms + pool-input scatters --------------------------
__global__ void k_hist(const int* __restrict__ ei, const int* __restrict__ ei2,
                       const int* __restrict__ cl1, const float* __restrict__ pos,
                       const int* __restrict__ batch) {
    int t = blockIdx.x * blockDim.x + threadIdx.x;
    if (t < Ee)  atomicAdd(&gz.degD1[ei[Ee + t]], 1);
    if (t < E2n) atomicAdd(&gz.degD2[ei2[E2n + t]], 1);
    if (t < Nn) {
        int c = cl1[t];
        atomicAdd(&gz.cntc1[c], 1);
        atomicAdd(&gz.possum[c * 3],     pos[t * 3]);
        atomicAdd(&gz.possum[c * 3 + 1], pos[t * 3 + 1]);
        atomicAdd(&gz.possum[c * 3 + 2], pos[t * 3 + 2]);
        atomicMax(&gf.batchp[c], batch[t]);
    }
}

// ---------------- K2: exclusive scans (2 arrays, 4 elems/thread) ----------------
__global__ void k_scan() {
    const int* deg; int* off; int* cur; int n;
    if (blockIdx.x == 0) { deg = gz.degD1; off = g_offD1; cur = g_curD1; n = Nn; }
    else                 { deg = gz.degD2; off = g_offD2; cur = g_curD2; n = C1n; }
    __shared__ int wsum[32];
    __shared__ int carry;
    int tid = threadIdx.x, lane = tid & 31, wid = tid >> 5;
    if (tid == 0) carry = 0;
    __syncthreads();
    for (int base = 0; base < n; base += 4096) {
        int i0 = base + tid * 4;
        int v[4];
#pragma unroll
        for (int k = 0; k < 4; k++) v[k] = (i0 + k < n) ? deg[i0 + k] : 0;
        int s = v[0] + v[1] + v[2] + v[3];
        int incl = s;
#pragma unroll
        for (int o = 1; o < 32; o <<= 1) {
            int tt = __shfl_up_sync(0xffffffffu, incl, o);
            if (lane >= o) incl += tt;
        }
        if (lane == 31) wsum[wid] = incl;
        __syncthreads();
        if (wid == 0) {
            int t2 = wsum[lane];
#pragma unroll
            for (int o = 1; o < 32; o <<= 1) {
                int tt = __shfl_up_sync(0xffffffffu, t2, o);
                if (lane >= o) t2 += tt;
            }
            wsum[lane] = t2;
        }
        __syncthreads();
        int woff = (wid == 0) ? 0 : wsum[wid - 1];
        int run = carry + woff + incl - s;
#pragma unroll
        for (int k = 0; k < 4; k++) {
            if (i0 + k < n) { off[i0 + k] = run; cur[i0 + k] = run; }
            run += v[k];
        }
        __syncthreads();
        if (tid == 0) carry += wsum[31];
        __syncthreads();
    }
    if (threadIdx.x == 0) off[n] = carry;
}

// ---------------- K3: scatter + fused maxabs ------------------------------------
__global__ void k_scat(const int* __restrict__ ei, const int* __restrict__ ei2,
                       const float* __restrict__ ea) {
    int t = blockIdx.x * blockDim.x + threadIdx.x;
    if (t < Ee) {
        int p = atomicAdd(&g_curD1[ei[Ee + t]], 1);
        float4 v;
        v.x = ea[3 * t]; v.y = ea[3 * t + 1]; v.z = ea[3 * t + 2];
        v.w = __int_as_float(ei[t]);
        g_e4[p] = v;
    }
    float m = 0.f;
    if (t < E2n) {
        int s = ei2[t], d = ei2[E2n + t];
        int p = atomicAdd(&g_curD2[d], 1);
        g_csrD2s[p] = s;
        float is = 1.f / fmaxf((float)gz.cntc1[s], 1.f);
        float id = 1.f / fmaxf((float)gz.cntc1[d], 1.f);
#pragma unroll
        for (int k = 0; k < 3; k++)
            m = fmaxf(m, fabsf(gz.possum[s * 3 + k] * is - gz.possum[d * 3 + k] * id));
    }
#pragma unroll
    for (int o = 16; o; o >>= 1) m = fmaxf(m, __shfl_xor_sync(0xffffffffu, m, o));
    if ((threadIdx.x & 31) == 0 && m > 0.f) atomicMax((int*)&gz.maxabs, __float_as_int(m));
}

// ---------------- K4: conv1 edge pass -> T1 (warp per dst, edge loop x2) --------
__global__ void __launch_bounds__(256) k_conv1(
        const float* __restrict__ x,
        const float* __restrict__ w1a, const float* __restrict__ b1a) {
    int tid = threadIdx.x;
    int d = (blockIdx.x * blockDim.x + tid) >> 5;
    int lane = tid & 31;
    if (d >= Nn) return;
    float wa0 = 0.f, wa1 = 0.f, wa2 = 0.f, ba = 0.f;
    if (lane < 25) { wa0 = w1a[lane]; wa1 = w1a[25 + lane]; wa2 = w1a[50 + lane]; ba = b1a[lane]; }
    else if (lane == 25) ba = 1.f;   // h == 1 -> x-sum (bias) row
    float acc0 = 0.f, acc1 = 0.f, acc2 = 0.f, acc3 = 0.f, acc4 = 0.f, acc5 = 0.f;
    int p0 = g_offD1[d], p1 = g_offD1[d + 1];
    int p = p0;
    for (; p + 1 < p1; p += 2) {
        float4 eA = g_e4[p];
        float4 eB = g_e4[p + 1];
        const float2* xA = (const float2*)(x + __float_as_int(eA.w) * 6);
        const float2* xB = (const float2*)(x + __float_as_int(eB.w) * 6);
        float2 a01 = xA[0], a23 = xA[1], a45 = xA[2];
        float2 b01 = xB[0], b23 = xB[1], b45 = xB[2];
        float hA = fmaxf(fmaf(eA.x, wa0, fmaf(eA.y, wa1, fmaf(eA.z, wa2, ba))), 0.f);
        float hB = fmaxf(fmaf(eB.x, wa0, fmaf(eB.y, wa1, fmaf(eB.z, wa2, ba))), 0.f);
        acc0 = fmaf(hA, a01.x, fmaf(hB, b01.x, acc0));
        acc1 = fmaf(hA, a01.y, fmaf(hB, b01.y, acc1));
        acc2 = fmaf(hA, a23.x, fmaf(hB, b23.x, acc2));
        acc3 = fmaf(hA, a23.y, fmaf(hB, b23.y, acc3));
        acc4 = fmaf(hA, a45.x, fmaf(hB, b45.x, acc4));
        acc5 = fmaf(hA, a45.y, fmaf(hB, b45.y, acc5));
    }
    if (p < p1) {
        float4 e4 = g_e4[p];
        const float2* xs = (const float2*)(x + __float_as_int(e4.w) * 6);
        float2 x01 = xs[0], x23 = xs[1], x45 = xs[2];
        float h = fmaxf(fmaf(e4.x, wa0, fmaf(e4.y, wa1, fmaf(e4.z, wa2, ba))), 0.f);
        acc0 = fmaf(h, x01.x, acc0); acc1 = fmaf(h, x01.y, acc1);
        acc2 = fmaf(h, x23.x, acc2); acc3 = fmaf(h, x23.y, acc3);
        acc4 = fmaf(h, x45.x, acc4); acc5 = fmaf(h, x45.y, acc5);
    }
    float invd = 1.f / fmaxf((float)(p1 - p0), 1.f);
    float* Trow = g_T1 + (size_t)d * T1S + lane * 6;
    if (lane < 26) {
        Trow[0] = acc0 * invd; Trow[1] = acc1 * invd; Trow[2] = acc2 * invd;
        Trow[3] = acc3 * invd; Trow[4] = acc4 * invd; Trow[5] = acc5 * invd;
    } else if (lane == 26) {
#pragma unroll
        for (int i = 0; i < 6; i++) Trow[i] = x[d * 6 + i];
    }
}

// ---------------- K5: gemm1  out = T1 @ [w1b|b1b|root1] + bias1 -> elu -> pool1 --
__global__ void __launch_bounds__(256) k_gemm1(
        const float* __restrict__ w1b, const float* __restrict__ b1b,
        const float* __restrict__ root1, const float* __restrict__ bias1,
        const int* __restrict__ cl1) {
    __shared__ __align__(16) float Ws[192 * 32];
    __shared__ __align__(16) float Ts[32 * 136];
    int tid = threadIdx.x;
    int nb = blockIdx.x * 128;
    for (int idx = tid; idx < 192 * 32; idx += 256) {
        float v = 0.f;
        if (idx < 4800)      v = w1b[idx];
        else if (idx < 4992) v = b1b[idx - 4800];
        else if (idx < 5184) v = root1[idx - 4992];
        Ws[idx] = v;
    }
    int cg = tid & 7, ng = tid >> 3;
    int c4 = cg * 4, n4 = ng * 4;
    float acc[4][4];
#pragma unroll
    for (int a = 0; a < 4; a++)
#pragma unroll
        for (int b = 0; b < 4; b++) acc[a][b] = 0.f;
    for (int kk = 0; kk < K1; kk += 32) {
        __syncthreads();
        for (int idx = tid; idx < 128 * 32; idx += 256) {
            int n = idx >> 5, k = idx & 31;
            float v = 0.f;
            if (kk + k < K1 && nb + n < Nn) v = g_T1[(size_t)(nb + n) * T1S + kk + k];
            Ts[k * 136 + n] = v;
        }
        __syncthreads();
#pragma unroll 8
        for (int k = 0; k < 32; k++) {
            float4 tv = *(const float4*)&Ts[k * 136 + n4];
            float4 wv = *(const float4*)&Ws[(kk + k) * 32 + c4];
            float ta[4] = {tv.x, tv.y, tv.z, tv.w};
            float wa[4] = {wv.x, wv.y, wv.z, wv.w};
#pragma unroll
            for (int a = 0; a < 4; a++)
#pragma unroll
                for (int b = 0; b < 4; b++) acc[a][b] = fmaf(ta[a], wa[b], acc[a][b]);
        }
    }
#pragma unroll
    for (int a = 0; a < 4; a++) {
        int n = nb + n4 + a;
        if (n >= Nn) continue;
        int c = cl1[n];
#pragma unroll
        for (int b = 0; b < 4; b++) {
            float v = elu1(acc[a][b] + bias1[c4 + b]);
            atomicMaxFloat(&gf.xp[c * 32 + c4 + b], v);
        }
    }
}

// ---------------- K6: conv2 edge pass -> T2 (warp per dst, edge loop x2) ---------
__global__ void __launch_bounds__(256) k_conv2(
        const float* __restrict__ w2a, const float* __restrict__ b2a) {
    int tid = threadIdx.x;
    int d = (blockIdx.x * blockDim.x + tid) >> 5;
    int lane = tid & 31;
    if (d >= C1n) return;
    float wa0 = 0.f, wa1 = 0.f, wa2 = 0.f, ba = 0.f;
    if (lane < 25) { wa0 = w2a[lane]; wa1 = w2a[25 + lane]; wa2 = w2a[50 + lane]; ba = b2a[lane]; }
    else if (lane == 25) ba = 1.f;
    float invcd = 1.f / fmaxf((float)gz.cntc1[d], 1.f);
    float pd0 = gz.possum[d * 3] * invcd, pd1 = gz.possum[d * 3 + 1] * invcd,
          pd2 = gz.possum[d * 3 + 2] * invcd;
    float inv = 0.5f / gz.maxabs;
    float acc[26];
#pragma unroll
    for (int r = 0; r < 26; r++) acc[r] = 0.f;
    int p0 = g_offD2[d], p1 = g_offD2[d + 1];
    int p = p0;
    for (; p + 1 < p1; p += 2) {
        int srcA = g_csrD2s[p];
        int srcB = g_csrD2s[p + 1];
        float icA = 1.f / fmaxf((float)gz.cntc1[srcA], 1.f);
        float icB = 1.f / fmaxf((float)gz.cntc1[srcB], 1.f);
        float xpA = fixneg(gf.xp[srcA * 32 + lane]);
        float xpB = fixneg(gf.xp[srcB * 32 + lane]);
        float a0 = fmaf(gz.possum[srcA * 3] * icA - pd0,     inv, 0.5f);
        float a1 = fmaf(gz.possum[srcA * 3 + 1] * icA - pd1, inv, 0.5f);
        float a2 = fmaf(gz.possum[srcA * 3 + 2] * icA - pd2, inv, 0.5f);
        float b0 = fmaf(gz.possum[srcB * 3] * icB - pd0,     inv, 0.5f);
        float b1 = fmaf(gz.possum[srcB * 3 + 1] * icB - pd1, inv, 0.5f);
        float b2 = fmaf(gz.possum[srcB * 3 + 2] * icB - pd2, inv, 0.5f);
        float hA = fmaxf(fmaf(a0, wa0, fmaf(a1, wa1, fmaf(a2, wa2, ba))), 0.f);
        float hB = fmaxf(fmaf(b0, wa0, fmaf(b1, wa1, fmaf(b2, wa2, ba))), 0.f);
#pragma unroll
        for (int r = 0; r < 26; r++) {
            float hrA = __shfl_sync(0xffffffffu, hA, r);
            float hrB = __shfl_sync(0xffffffffu, hB, r);
            acc[r] = fmaf(hrA, xpA, fmaf(hrB, xpB, acc[r]));
        }
    }
    if (p < p1) {
        int src = g_csrD2s[p];
        float invcs = 1.f / fmaxf((float)gz.cntc1[src], 1.f);
        float xpi = fixneg(gf.xp[src * 32 + lane]);
        float e0 = fmaf(gz.possum[src * 3] * invcs - pd0,     inv, 0.5f);
        float e1 = fmaf(gz.possum[src * 3 + 1] * invcs - pd1, inv, 0.5f);
        float e2 = fmaf(gz.possum[src * 3 + 2] * invcs - pd2, inv, 0.5f);
        float h = fmaxf(fmaf(e0, wa0, fmaf(e1, wa1, fmaf(e2, wa2, ba))), 0.f);
#pragma unroll
        for (int r = 0; r < 26; r++) {
            float hr = __shfl_sync(0xffffffffu, h, r);
            acc[r] = fmaf(hr, xpi, acc[r]);
        }
    }
    float invd = 1.f / fmaxf((float)(p1 - p0), 1.f);
    float* Trow = g_T2 + (size_t)d * T2S;
#pragma unroll
    for (int r = 0; r < 26; r++) Trow[r * 32 + lane] = acc[r] * invd;
    Trow[832 + lane] = fixneg(gf.xp[d * 32 + lane]);   // root columns
}

// ---------------- K7: gemm2 scalar, 8 cols x 4 nodes per thread ------------------
// 256 thr: 8 col-groups (8 cols) x 32 node-groups (4 nodes); 128-node tile.
__global__ void __launch_bounds__(256) k_gemm2(
        const float* __restrict__ w2b, const float* __restrict__ b2b,
        const float* __restrict__ root2, const float* __restrict__ bias2,
        const int* __restrict__ cl2) {
    __shared__ __align__(16) float Ws[32 * 64];      // [k][c]
    __shared__ __align__(16) float Ts[32 * 132];     // [k][n], stride 132
    int tid = threadIdx.x;
    int nb = blockIdx.x * 128;
    int cg = tid & 7, ng = tid >> 3;
    int c8 = cg * 8, n4 = ng * 4;
    float acc[4][8];
#pragma unroll
    for (int a = 0; a < 4; a++)
#pragma unroll
        for (int b = 0; b < 8; b++) acc[a][b] = 0.f;
    for (int kk = 0; kk < K2; kk += 32) {
        __syncthreads();
        for (int idx = tid; idx < 2048; idx += 256) {
            int k = kk + (idx >> 6), c = idx & 63;
            float v;
            if (k < 800)      v = w2b[k * 64 + c];
            else if (k < 832) v = b2b[(k - 800) * 64 + c];
            else              v = root2[(k - 832) * 64 + c];
            Ws[idx] = v;
        }
        for (int idx = tid; idx < 128 * 32; idx += 256) {
            int n = idx >> 5, k = idx & 31;
            float tv = (nb + n < C1n) ? g_T2[(size_t)(nb + n) * T2S + kk + k] : 0.f;
            Ts[k * 132 + n] = tv;
        }
        __syncthreads();
#pragma unroll 4
        for (int k = 0; k < 32; k++) {
            float4 tv = *(const float4*)&Ts[k * 132 + n4];
            float4 w0 = *(const float4*)&Ws[k * 64 + c8];
            float4 w1 = *(const float4*)&Ws[k * 64 + c8 + 4];
            float ta[4] = {tv.x, tv.y, tv.z, tv.w};
            float wa[8] = {w0.x, w0.y, w0.z, w0.w, w1.x, w1.y, w1.z, w1.w};
#pragma unroll
            for (int a = 0; a < 4; a++)
#pragma unroll
                for (int b = 0; b < 8; b++) acc[a][b] = fmaf(ta[a], wa[b], acc[a][b]);
        }
    }
#pragma unroll
    for (int a = 0; a < 4; a++) {
        int n = nb + n4 + a;
        if (n >= C1n) continue;
        int c2 = cl2[n];
#pragma unroll
        for (int b = 0; b < 8; b++) {
            float v = elu1(acc[a][b] + bias2[c8 + b]);
            atomicMaxFloat(&gf.x3[c2 * 64 + c8 + b], v);
        }
        if (cg == 0) atomicMax(&gf.batch2[c2], max(gf.batchp[n], 0));
    }
}

// ---------------- K8: pool2 finalize + global mean scatter ----------------------
__global__ void k_pool2() {
    int c = (blockIdx.x * blockDim.x + threadIdx.x) >> 5;
    int lane = threadIdx.x & 31;
    if (c >= C2n) return;
    float v0 = fixneg(gf.x3[c * 64 + lane]);
    float v1 = fixneg(gf.x3[c * 64 + lane + 32]);
    int b = max(gf.batch2[c], 0);
    atomicAdd(&gz.gsum[b * 64 + lane], v0);
    atomicAdd(&gz.gsum[b * 64 + lane + 32], v1);
    if (lane == 0) atomicAdd(&gz.gcnt[b], 1.f);
}

// ---------------- K9: FC head + log_softmax ------------------------------------
__global__ void k_head(const float* __restrict__ fc1w, const float* __restrict__ fc1b,
                       const float* __restrict__ fc2w, const float* __restrict__ fc2b,
                       float* __restrict__ out) {
    __shared__ float g[16 * 64];
    __shared__ float hh[16 * 128];
    __shared__ float lg[16 * 10];
    int tid = threadIdx.x;
    for (int i = tid; i < 16 * 64; i += 256) g[i] = gz.gsum[i] / fmaxf(gz.gcnt[i >> 6], 1.f);
    __syncthreads();
    for (int o = tid; o < 16 * 128; o += 256) {
        int b = o >> 7, j = o & 127;
        float acc = fc1b[j];
        for (int k = 0; k < 64; k++) acc = fmaf(g[b * 64 + k], fc1w[k * 128 + j], acc);
        hh[o] = elu1(acc);
    }
    __syncthreads();
    if (tid < 160) {
        int b = tid / 10, k = tid % 10;
        float acc = fc2b[k];
        for (int j = 0; j < 128; j++) acc = fmaf(hh[b * 128 + j], fc2w[j * 10 + k], acc);
        lg[tid] = acc;
    }
    __syncthreads();
    if (tid < 16) {
        float m = -1e30f;
        for (int k = 0; k < 10; k++) m = fmaxf(m, lg[tid * 10 + k]);
        float s = 0.f;
        for (int k = 0; k < 10; k++) s += expf(lg[tid * 10 + k] - m);
        float ls = logf(s) + m;
        for (int k = 0; k < 10; k++) out[tid * 10 + k] = lg[tid * 10 + k] - ls;
    }
}

// ---------------- host launcher --------------------------------------------------
extern "C" void kernel_launch(void* const* d_in, const int* in_sizes, int n_in,
                              void* d_out, int out_size) {
    const float *x, *ea, *pos, *w1a, *b1a, *w1b, *b1b, *root1, *bias1;
    const float *w2a, *b2a, *w2b, *b2b, *root2, *bias2, *fc1w, *fc1b, *fc2w, *fc2b;
    const int *ei, *batch, *cl1, *ei2, *cl2;

    if (in_sizes[3] == 2 * Ee) {
        x = (const float*)d_in[0];  ea = (const float*)d_in[1];  pos = (const float*)d_in[2];
        ei = (const int*)d_in[3];   batch = (const int*)d_in[4]; cl1 = (const int*)d_in[5];
        ei2 = (const int*)d_in[6];  cl2 = (const int*)d_in[7];
        w1a = (const float*)d_in[8];  b1a = (const float*)d_in[9];
        w1b = (const float*)d_in[10]; b1b = (const float*)d_in[11];
        root1 = (const float*)d_in[12]; bias1 = (const float*)d_in[13];
        w2a = (const float*)d_in[14]; b2a = (const float*)d_in[15];
        w2b = (const float*)d_in[16]; b2b = (const float*)d_in[17];
        root2 = (const float*)d_in[18]; bias2 = (const float*)d_in[19];
        fc1w = (const float*)d_in[20]; fc1b = (const float*)d_in[21];
        fc2w = (const float*)d_in[22]; fc2b = (const float*)d_in[23];
    } else {
        x = (const float*)d_in[0];  ea = (const float*)d_in[1];  pos = (const float*)d_in[2];
        w1a = (const float*)d_in[3];  b1a = (const float*)d_in[4];
        w1b = (const float*)d_in[5];  b1b = (const float*)d_in[6];
        root1 = (const float*)d_in[7]; bias1 = (const float*)d_in[8];
        w2a = (const float*)d_in[9];  b2a = (const float*)d_in[10];
        w2b = (const float*)d_in[11]; b2b = (const float*)d_in[12];
        root2 = (const float*)d_in[13]; bias2 = (const float*)d_in[14];
        fc1w = (const float*)d_in[15]; fc1b = (const float*)d_in[16];
        fc2w = (const float*)d_in[17]; fc2b = (const float*)d_in[18];
        ei = (const int*)d_in[19];  batch = (const int*)d_in[20]; cl1 = (const int*)d_in[21];
        ei2 = (const int*)d_in[22]; cl2 = (const int*)d_in[23];
    }

    void *pz = nullptr, *pf = nullptr;
    cudaGetSymbolAddress(&pz, gz);
    cudaGetSymbolAddress(&pf, gf);
    cudaMemsetAsync(pz, 0, sizeof(ZBlk));
    cudaMemsetAsync(pf, 0xff, sizeof(FBlk));

    k_hist<<<(Ee + 255) / 256, 256>>>(ei, ei2, cl1, pos, batch);
    k_scan<<<2, 1024>>>();
    k_scat<<<(Ee + 255) / 256, 256>>>(ei, ei2, ea);
    k_conv1<<<3750, 256>>>(x, w1a, b1a);
    k_gemm1<<<(Nn + 127) / 128, 256>>>(w1b, b1b, root1, bias1, cl1);
    k_conv2<<<1875, 256>>>(w2a, b2a);
    k_gemm2<<<(C1n + 127) / 128, 256>>>(w2b, b2b, root2, bias2, cl2);
    k_pool2<<<938, 256>>>();
    k_head<<<1, 256>>>(fc1w, fc1b, fc2w, fc2b, (float*)d_out);
}

// round 14
// speedup vs baseline: 1.1322x; 1.1322x over previous
#include <cuda_runtime.h>
#include <math.h>
#include <limits.h>

#define Nn 30000
#define Ee 400000
#define C1n 15000
#define E2n 100000
#define C2n 7500
#define Bn 16

#define T1S 168   // T1 row stride (162 used)
#define K1 162    // 150 w1b + 6 b1b + 6 root1
#define T2S 864   // T2 row stride
#define K2 864    // 800 w2b + 32 b2b + 32 root2

typedef unsigned long long ull;

// ---------------- zero-init block (single memset 0) ---------------------------
struct ZBlk {
    int   degD1[Nn];
    int   degD2[C1n], cntc1[C1n];
    float possum[C1n * 3];
    float gsum[Bn * 64];
    float gcnt[Bn];
    float maxabs;
};
// ---------------- 0xff-init block (single memset 0xff) ------------------------
struct FBlk {
    float xp[C1n * 32];      // 0xffffffff sentinel (loses to all atomicMaxFloat)
    float x3[C2n * 64];
    int   batchp[C1n];       // -1
    int   batch2[C2n];       // -1
};
__device__ ZBlk gz;
__device__ FBlk gf;

// ---------------- uninitialized scratch ----------------------------------------
__device__ int g_offD1[Nn + 1], g_curD1[Nn];
__device__ int g_offD2[C1n + 1], g_curD2[C1n];
__device__ __align__(16) float4 g_e4[Ee];          // {ea0,ea1,ea2, src-bits} dst-sorted
__device__ int g_csrD2s[E2n];                      // src ids dst-sorted
__device__ __align__(16) float4 g_posn[C1n];       // normalized cluster positions
__device__ __align__(16) float g_T1[(size_t)Nn * T1S];
__device__ __align__(16) float g_T2[(size_t)C1n * T2S];

__device__ __forceinline__ void atomicMaxFloat(float* addr, float val) {
    if (val >= 0.f) atomicMax((int*)addr, __float_as_int(val));
    else            atomicMin((unsigned int*)addr, __float_as_uint(val));
}
__device__ __forceinline__ float elu1(float v) { return v > 0.f ? v : expm1f(v); }
__device__ __forceinline__ float fixneg(float v) { return (v > -3e38f) ? v : 0.f; }

// ---------------- K1: histograms + pool-input scatters --------------------------
__global__ void k_hist(const int* __restrict__ ei, const int* __restrict__ ei2,
                       const int* __restrict__ cl1, const float* __restrict__ pos,
                       const int* __restrict__ batch) {
    int t = blockIdx.x * blockDim.x + threadIdx.x;
    if (t < Ee)  atomicAdd(&gz.degD1[ei[Ee + t]], 1);
    if (t < E2n) atomicAdd(&gz.degD2[ei2[E2n + t]], 1);
    if (t < Nn) {
        int c = cl1[t];
        atomicAdd(&gz.cntc1[c], 1);
        atomicAdd(&gz.possum[c * 3],     pos[t * 3]);
        atomicAdd(&gz.possum[c * 3 + 1], pos[t * 3 + 1]);
        atomicAdd(&gz.possum[c * 3 + 2], pos[t * 3 + 2]);
        atomicMax(&gf.batchp[c], batch[t]);
    }
}

// ---------------- K2: exclusive scans (2 arrays, 4 elems/thread) ----------------
__global__ void k_scan() {
    const int* deg; int* off; int* cur; int n;
    if (blockIdx.x == 0) { deg = gz.degD1; off = g_offD1; cur = g_curD1; n = Nn; }
    else                 { deg = gz.degD2; off = g_offD2; cur = g_curD2; n = C1n; }
    __shared__ int wsum[32];
    __shared__ int carry;
    int tid = threadIdx.x, lane = tid & 31, wid = tid >> 5;
    if (tid == 0) carry = 0;
    __syncthreads();
    for (int base = 0; base < n; base += 4096) {
        int i0 = base + tid * 4;
        int v[4];
#pragma unroll
        for (int k = 0; k < 4; k++) v[k] = (i0 + k < n) ? deg[i0 + k] : 0;
        int s = v[0] + v[1] + v[2] + v[3];
        int incl = s;
#pragma unroll
        for (int o = 1; o < 32; o <<= 1) {
            int tt = __shfl_up_sync(0xffffffffu, incl, o);
            if (lane >= o) incl += tt;
        }
        if (lane == 31) wsum[wid] = incl;
        __syncthreads();
        if (wid == 0) {
            int t2 = wsum[lane];
#pragma unroll
            for (int o = 1; o < 32; o <<= 1) {
                int tt = __shfl_up_sync(0xffffffffu, t2, o);
                if (lane >= o) t2 += tt;
            }
            wsum[lane] = t2;
        }
        __syncthreads();
        int woff = (wid == 0) ? 0 : wsum[wid - 1];
        int run = carry + woff + incl - s;
#pragma unroll
        for (int k = 0; k < 4; k++) {
            if (i0 + k < n) { off[i0 + k] = run; cur[i0 + k] = run; }
            run += v[k];
        }
        __syncthreads();
        if (tid == 0) carry += wsum[31];
        __syncthreads();
    }
    if (threadIdx.x == 0) off[n] = carry;
}

// ---------------- K3: scatter + posn + fused maxabs ------------------------------
__global__ void k_scat(const int* __restrict__ ei, const int* __restrict__ ei2,
                       const float* __restrict__ ea) {
    int t = blockIdx.x * blockDim.x + threadIdx.x;
    if (t < Ee) {
        int p = atomicAdd(&g_curD1[ei[Ee + t]], 1);
        float4 v;
        v.x = ea[3 * t]; v.y = ea[3 * t + 1]; v.z = ea[3 * t + 2];
        v.w = __int_as_float(ei[t]);
        g_e4[p] = v;
    }
    if (t < C1n) {
        float ic = 1.f / fmaxf((float)gz.cntc1[t], 1.f);
        float4 pn;
        pn.x = gz.possum[t * 3] * ic;
        pn.y = gz.possum[t * 3 + 1] * ic;
        pn.z = gz.possum[t * 3 + 2] * ic;
        pn.w = 0.f;
        g_posn[t] = pn;
    }
    float m = 0.f;
    if (t < E2n) {
        int s = ei2[t], d = ei2[E2n + t];
        int p = atomicAdd(&g_curD2[d], 1);
        g_csrD2s[p] = s;
        float is = 1.f / fmaxf((float)gz.cntc1[s], 1.f);
        float id = 1.f / fmaxf((float)gz.cntc1[d], 1.f);
#pragma unroll
        for (int k = 0; k < 3; k++)
            m = fmaxf(m, fabsf(gz.possum[s * 3 + k] * is - gz.possum[d * 3 + k] * id));
    }
#pragma unroll
    for (int o = 16; o; o >>= 1) m = fmaxf(m, __shfl_xor_sync(0xffffffffu, m, o));
    if ((threadIdx.x & 31) == 0 && m > 0.f) atomicMax((int*)&gz.maxabs, __float_as_int(m));
}

// ---------------- K4: conv1 edge pass -> T1 (warp per dst node, R12-proven) -----
__global__ void __launch_bounds__(256) k_conv1(
        const float* __restrict__ x,
        const float* __restrict__ w1a, const float* __restrict__ b1a) {
    int tid = threadIdx.x;
    int d = (blockIdx.x * blockDim.x + tid) >> 5;
    int lane = tid & 31;
    if (d >= Nn) return;
    float wa0 = 0.f, wa1 = 0.f, wa2 = 0.f, ba = 0.f;
    if (lane < 25) { wa0 = w1a[lane]; wa1 = w1a[25 + lane]; wa2 = w1a[50 + lane]; ba = b1a[lane]; }
    else if (lane == 25) ba = 1.f;   // h == 1 -> x-sum (bias) row
    float acc0 = 0.f, acc1 = 0.f, acc2 = 0.f, acc3 = 0.f, acc4 = 0.f, acc5 = 0.f;
    int p0 = g_offD1[d], p1 = g_offD1[d + 1];
    for (int p = p0; p < p1; p++) {
        float4 e4 = g_e4[p];
        int src = __float_as_int(e4.w);
        const float2* xs = (const float2*)(x + src * 6);
        float2 x01 = xs[0], x23 = xs[1], x45 = xs[2];
        float h = fmaxf(fmaf(e4.x, wa0, fmaf(e4.y, wa1, fmaf(e4.z, wa2, ba))), 0.f);
        acc0 = fmaf(h, x01.x, acc0); acc1 = fmaf(h, x01.y, acc1);
        acc2 = fmaf(h, x23.x, acc2); acc3 = fmaf(h, x23.y, acc3);
        acc4 = fmaf(h, x45.x, acc4); acc5 = fmaf(h, x45.y, acc5);
    }
    float invd = 1.f / fmaxf((float)(p1 - p0), 1.f);
    float* Trow = g_T1 + (size_t)d * T1S + lane * 6;
    if (lane < 26) {
        Trow[0] = acc0 * invd; Trow[1] = acc1 * invd; Trow[2] = acc2 * invd;
        Trow[3] = acc3 * invd; Trow[4] = acc4 * invd; Trow[5] = acc5 * invd;
    } else if (lane == 26) {
#pragma unroll
        for (int i = 0; i < 6; i++) Trow[i] = x[d * 6 + i];
    }
}

// ---------------- K5: gemm1  out = T1 @ [w1b|b1b|root1] + bias1 -> elu -> pool1 --
__global__ void __launch_bounds__(256) k_gemm1(
        const float* __restrict__ w1b, const float* __restrict__ b1b,
        const float* __restrict__ root1, const float* __restrict__ bias1,
        const int* __restrict__ cl1) {
    __shared__ __align__(16) float Ws[192 * 32];
    __shared__ __align__(16) float Ts[32 * 136];
    int tid = threadIdx.x;
    int nb = blockIdx.x * 128;
    for (int idx = tid; idx < 192 * 32; idx += 256) {
        float v = 0.f;
        if (idx < 4800)      v = w1b[idx];
        else if (idx < 4992) v = b1b[idx - 4800];
        else if (idx < 5184) v = root1[idx - 4992];
        Ws[idx] = v;
    }
    int cg = tid & 7, ng = tid >> 3;
    int c4 = cg * 4, n4 = ng * 4;
    float acc[4][4];
#pragma unroll
    for (int a = 0; a < 4; a++)
#pragma unroll
        for (int b = 0; b < 4; b++) acc[a][b] = 0.f;
    for (int kk = 0; kk < K1; kk += 32) {
        __syncthreads();
        for (int idx = tid; idx < 128 * 32; idx += 256) {
            int n = idx >> 5, k = idx & 31;
            float v = 0.f;
            if (kk + k < K1 && nb + n < Nn) v = g_T1[(size_t)(nb + n) * T1S + kk + k];
            Ts[k * 136 + n] = v;
        }
        __syncthreads();
#pragma unroll 8
        for (int k = 0; k < 32; k++) {
            float4 tv = *(const float4*)&Ts[k * 136 + n4];
            float4 wv = *(const float4*)&Ws[(kk + k) * 32 + c4];
            float ta[4] = {tv.x, tv.y, tv.z, tv.w};
            float wa[4] = {wv.x, wv.y, wv.z, wv.w};
#pragma unroll
            for (int a = 0; a < 4; a++)
#pragma unroll
                for (int b = 0; b < 4; b++) acc[a][b] = fmaf(ta[a], wa[b], acc[a][b]);
        }
    }
#pragma unroll
    for (int a = 0; a < 4; a++) {
        int n = nb + n4 + a;
        if (n >= Nn) continue;
        int c = cl1[n];
#pragma unroll
        for (int b = 0; b < 4; b++) {
            float v = elu1(acc[a][b] + bias1[c4 + b]);
            atomicMaxFloat(&gf.xp[c * 32 + c4 + b], v);
        }
    }
}

// ---------------- K6: conv2 edge pass -> T2 (warp per dst, posn float4) ----------
__global__ void __launch_bounds__(256) k_conv2(
        const float* __restrict__ w2a, const float* __restrict__ b2a) {
    int tid = threadIdx.x;
    int d = (blockIdx.x * blockDim.x + tid) >> 5;
    int lane = tid & 31;
    if (d >= C1n) return;
    float wa0 = 0.f, wa1 = 0.f, wa2 = 0.f, ba = 0.f;
    if (lane < 25) { wa0 = w2a[lane]; wa1 = w2a[25 + lane]; wa2 = w2a[50 + lane]; ba = b2a[lane]; }
    else if (lane == 25) ba = 1.f;
    float4 pdn = g_posn[d];
    float inv = 0.5f / gz.maxabs;
    float acc[26];
#pragma unroll
    for (int r = 0; r < 26; r++) acc[r] = 0.f;
    int p0 = g_offD2[d], p1 = g_offD2[d + 1];
    for (int p = p0; p < p1; p++) {
        int src = g_csrD2s[p];
        float4 ps = g_posn[src];
        float xpi = fixneg(gf.xp[src * 32 + lane]);
        float e0 = fmaf(ps.x - pdn.x, inv, 0.5f);
        float e1 = fmaf(ps.y - pdn.y, inv, 0.5f);
        float e2 = fmaf(ps.z - pdn.z, inv, 0.5f);
        float h = fmaxf(fmaf(e0, wa0, fmaf(e1, wa1, fmaf(e2, wa2, ba))), 0.f);
#pragma unroll
        for (int r = 0; r < 26; r++) {
            float hr = __shfl_sync(0xffffffffu, h, r);
            acc[r] = fmaf(hr, xpi, acc[r]);
        }
    }
    float invd = 1.f / fmaxf((float)(p1 - p0), 1.f);
    float* Trow = g_T2 + (size_t)d * T2S;
#pragma unroll
    for (int r = 0; r < 26; r++) Trow[r * 32 + lane] = acc[r] * invd;
    Trow[832 + lane] = fixneg(gf.xp[d * 32 + lane]);   // root columns
}

// ---------------- K7: gemm2 scalar (R8/R12-proven) --------------------------------
__global__ void __launch_bounds__(256) k_gemm2(
        const float* __restrict__ w2b, const float* __restrict__ b2b,
        const float* __restrict__ root2, const float* __restrict__ bias2,
        const int* __restrict__ cl2) {
    __shared__ __align__(16) float Ws[64 * 64];
    __shared__ __align__(16) float Ts[64 * 68];
    int tid = threadIdx.x;
    int nb = blockIdx.x * 64;
    int cg = tid & 15, ng = tid >> 4;
    int c4 = cg * 4, n4 = ng * 4;
    float acc[4][4];
#pragma unroll
    for (int a = 0; a < 4; a++)
#pragma unroll
        for (int b = 0; b < 4; b++) acc[a][b] = 0.f;
    for (int kk = 0; kk < K2; kk += 64) {
        __syncthreads();
        for (int idx = tid; idx < 64 * 64; idx += 256) {
            int kr = idx >> 6, c = idx & 63;
            int k = kk + kr;
            float v;
            if (k < 800)      v = w2b[k * 64 + c];
            else if (k < 832) v = b2b[(k - 800) * 64 + c];
            else              v = root2[(k - 832) * 64 + c];
            Ws[idx] = v;
            int n = idx >> 6, kt = idx & 63;
            float tv = 0.f;
            if (nb + n < C1n) tv = g_T2[(size_t)(nb + n) * T2S + kk + kt];
            Ts[kt * 68 + n] = tv;
        }
        __syncthreads();
#pragma unroll 8
        for (int k = 0; k < 64; k++) {
            float4 tv = *(const float4*)&Ts[k * 68 + n4];
            float4 wv = *(const float4*)&Ws[k * 64 + c4];
            float ta[4] = {tv.x, tv.y, tv.z, tv.w};
            float wa[4] = {wv.x, wv.y, wv.z, wv.w};
#pragma unroll
            for (int a = 0; a < 4; a++)
#pragma unroll
                for (int b = 0; b < 4; b++) acc[a][b] = fmaf(ta[a], wa[b], acc[a][b]);
        }
    }
#pragma unroll
    for (int a = 0; a < 4; a++) {
        int n = nb + n4 + a;
        if (n >= C1n) continue;
        int c2 = cl2[n];
#pragma unroll
        for (int b = 0; b < 4; b++) {
            float v = elu1(acc[a][b] + bias2[c4 + b]);
            atomicMaxFloat(&gf.x3[c2 * 64 + c4 + b], v);
        }
        if (cg == 0) atomicMax(&gf.batch2[c2], max(gf.batchp[n], 0));
    }
}

// ---------------- K8: pool2 finalize + global mean scatter ----------------------
__global__ void k_pool2() {
    int c = (blockIdx.x * blockDim.x + threadIdx.x) >> 5;
    int lane = threadIdx.x & 31;
    if (c >= C2n) return;
    float v0 = fixneg(gf.x3[c * 64 + lane]);
    float v1 = fixneg(gf.x3[c * 64 + lane + 32]);
    int b = max(gf.batch2[c], 0);
    atomicAdd(&gz.gsum[b * 64 + lane], v0);
    atomicAdd(&gz.gsum[b * 64 + lane + 32], v1);
    if (lane == 0) atomicAdd(&gz.gcnt[b], 1.f);
}

// ---------------- K9: FC head + log_softmax ------------------------------------
__global__ void k_head(const float* __restrict__ fc1w, const float* __restrict__ fc1b,
                       const float* __restrict__ fc2w, const float* __restrict__ fc2b,
                       float* __restrict__ out) {
    __shared__ float g[16 * 64];
    __shared__ float hh[16 * 128];
    __shared__ float lg[16 * 10];
    int tid = threadIdx.x;
    for (int i = tid; i < 16 * 64; i += 256) g[i] = gz.gsum[i] / fmaxf(gz.gcnt[i >> 6], 1.f);
    __syncthreads();
    for (int o = tid; o < 16 * 128; o += 256) {
        int b = o >> 7, j = o & 127;
        float acc = fc1b[j];
        for (int k = 0; k < 64; k++) acc = fmaf(g[b * 64 + k], fc1w[k * 128 + j], acc);
        hh[o] = elu1(acc);
    }
    __syncthreads();
    if (tid < 160) {
        int b = tid / 10, k = tid % 10;
        float acc = fc2b[k];
        for (int j = 0; j < 128; j++) acc = fmaf(hh[b * 128 + j], fc2w[j * 10 + k], acc);
        lg[tid] = acc;
    }
    __syncthreads();
    if (tid < 16) {
        float m = -1e30f;
        for (int k = 0; k < 10; k++) m = fmaxf(m, lg[tid * 10 + k]);
        float s = 0.f;
        for (int k = 0; k < 10; k++) s += expf(lg[tid * 10 + k] - m);
        float ls = logf(s) + m;
        for (int k = 0; k < 10; k++) out[tid * 10 + k] = lg[tid * 10 + k] - ls;
    }
}

// ---------------- host launcher --------------------------------------------------
extern "C" void kernel_launch(void* const* d_in, const int* in_sizes, int n_in,
                              void* d_out, int out_size) {
    const float *x, *ea, *pos, *w1a, *b1a, *w1b, *b1b, *root1, *bias1;
    const float *w2a, *b2a, *w2b, *b2b, *root2, *bias2, *fc1w, *fc1b, *fc2w, *fc2b;
    const int *ei, *batch, *cl1, *ei2, *cl2;

    if (in_sizes[3] == 2 * Ee) {
        x = (const float*)d_in[0];  ea = (const float*)d_in[1];  pos = (const float*)d_in[2];
        ei = (const int*)d_in[3];   batch = (const int*)d_in[4]; cl1 = (const int*)d_in[5];
        ei2 = (const int*)d_in[6];  cl2 = (const int*)d_in[7];
        w1a = (const float*)d_in[8];  b1a = (const float*)d_in[9];
        w1b = (const float*)d_in[10]; b1b = (const float*)d_in[11];
        root1 = (const float*)d_in[12]; bias1 = (const float*)d_in[13];
        w2a = (const float*)d_in[14]; b2a = (const float*)d_in[15];
        w2b = (const float*)d_in[16]; b2b = (const float*)d_in[17];
        root2 = (const float*)d_in[18]; bias2 = (const float*)d_in[19];
        fc1w = (const float*)d_in[20]; fc1b = (const float*)d_in[21];
        fc2w = (const float*)d_in[22]; fc2b = (const float*)d_in[23];
    } else {
        x = (const float*)d_in[0];  ea = (const float*)d_in[1];  pos = (const float*)d_in[2];
        w1a = (const float*)d_in[3];  b1a = (const float*)d_in[4];
        w1b = (const float*)d_in[5];  b1b = (const float*)d_in[6];
        root1 = (const float*)d_in[7]; bias1 = (const float*)d_in[8];
        w2a = (const float*)d_in[9];  b2a = (const float*)d_in[10];
        w2b = (const float*)d_in[11]; b2b = (const float*)d_in[12];
        root2 = (const float*)d_in[13]; bias2 = (const float*)d_in[14];
        fc1w = (const float*)d_in[15]; fc1b = (const float*)d_in[16];
        fc2w = (const float*)d_in[17]; fc2b = (const float*)d_in[18];
        ei = (const int*)d_in[19];  batch = (const int*)d_in[20]; cl1 = (const int*)d_in[21];
        ei2 = (const int*)d_in[22]; cl2 = (const int*)d_in[23];
    }

    void *pz = nullptr, *pf = nullptr;
    cudaGetSymbolAddress(&pz, gz);
    cudaGetSymbolAddress(&pf, gf);
    cudaMemsetAsync(pz, 0, sizeof(ZBlk));
    cudaMemsetAsync(pf, 0xff, sizeof(FBlk));

    k_hist<<<(Ee + 255) / 256, 256>>>(ei, ei2, cl1, pos, batch);
    k_scan<<<2, 1024>>>();
    k_scat<<<(Ee + 255) / 256, 256>>>(ei, ei2, ea);
    k_conv1<<<3750, 256>>>(x, w1a, b1a);
    k_gemm1<<<(Nn + 127) / 128, 256>>>(w1b, b1b, root1, bias1, cl1);
    k_conv2<<<1875, 256>>>(w2a, b2a);
    k_gemm2<<<(C1n + 63) / 64, 256>>>(w2b, b2b, root2, bias2, cl2);
    k_pool2<<<938, 256>>>();
    k_head<<<1, 256>>>(fc1w, fc1b, fc2w, fc2b, (float*)d_out);
}

// round 15
// speedup vs baseline: 1.5387x; 1.3590x over previous
#include <cuda_runtime.h>
#include <math.h>
#include <limits.h>

#define Nn 30000
#define Ee 400000
#define C1n 15000
#define E2n 100000
#define C2n 7500
#define Bn 16

#define T1S 168   // T1 row stride (162 used)
#define K1 162    // 150 w1b + 6 b1b + 6 root1
#define T2S 864   // T2 row stride
#define K2 864    // 800 w2b + 32 b2b + 32 root2

typedef unsigned long long ull;

// ---------------- zero-init block (single memset 0) ---------------------------
struct ZBlk {
    int   degD1[Nn];
    int   degD2[C1n], cntc1[C1n];
    float possum[C1n * 3];
    float gsum[Bn * 64];
    float gcnt[Bn];
    float maxabs;
};
// ---------------- 0xff-init block (single memset 0xff) ------------------------
struct FBlk {
    float xp[C1n * 32];      // 0xffffffff sentinel (loses to all atomicMaxFloat)
    float x3[C2n * 64];
    int   batchp[C1n];       // -1
    int   batch2[C2n];       // -1
};
__device__ ZBlk gz;
__device__ FBlk gf;

// ---------------- uninitialized scratch ----------------------------------------
__device__ int g_offD1[Nn + 1], g_curD1[Nn];
__device__ int g_offD2[C1n + 1], g_curD2[C1n];
__device__ __align__(16) float4 g_e4[Ee];          // {ea0,ea1,ea2, src-bits} dst-sorted
__device__ int g_csrD2s[E2n];                      // src ids dst-sorted
__device__ __align__(16) float4 g_posn[C1n];       // normalized cluster positions
__device__ __align__(16) float g_T1[(size_t)Nn * T1S];
__device__ __align__(16) float g_T2[(size_t)C1n * T2S];

__device__ __forceinline__ void atomicMaxFloat(float* addr, float val) {
    if (val >= 0.f) atomicMax((int*)addr, __float_as_int(val));
    else            atomicMin((unsigned int*)addr, __float_as_uint(val));
}
__device__ __forceinline__ float elu1(float v) { return v > 0.f ? v : expm1f(v); }
__device__ __forceinline__ float fixneg(float v) { return (v > -3e38f) ? v : 0.f; }

__device__ __forceinline__ unsigned smem_u32(const void* p) {
    return (unsigned)__cvta_generic_to_shared(p);
}
__device__ __forceinline__ void cp16(unsigned dst, const void* src, int bytes) {
    asm volatile("cp.async.cg.shared.global [%0], [%1], 16, %2;"
                 :: "r"(dst), "l"(src), "r"(bytes));
}

// ---------------- K1: histograms + pool-input scatters --------------------------
__global__ void k_hist(const int* __restrict__ ei, const int* __restrict__ ei2,
                       const int* __restrict__ cl1, const float* __restrict__ pos,
                       const int* __restrict__ batch) {
    int t = blockIdx.x * blockDim.x + threadIdx.x;
    if (t < Ee)  atomicAdd(&gz.degD1[ei[Ee + t]], 1);
    if (t < E2n) atomicAdd(&gz.degD2[ei2[E2n + t]], 1);
    if (t < Nn) {
        int c = cl1[t];
        atomicAdd(&gz.cntc1[c], 1);
        atomicAdd(&gz.possum[c * 3],     pos[t * 3]);
        atomicAdd(&gz.possum[c * 3 + 1], pos[t * 3 + 1]);
        atomicAdd(&gz.possum[c * 3 + 2], pos[t * 3 + 2]);
        atomicMax(&gf.batchp[c], batch[t]);
    }
}

// ---------------- K2: exclusive scans (2 arrays, 4 elems/thread) ----------------
__global__ void k_scan() {
    const int* deg; int* off; int* cur; int n;
    if (blockIdx.x == 0) { deg = gz.degD1; off = g_offD1; cur = g_curD1; n = Nn; }
    else                 { deg = gz.degD2; off = g_offD2; cur = g_curD2; n = C1n; }
    __shared__ int wsum[32];
    __shared__ int carry;
    int tid = threadIdx.x, lane = tid & 31, wid = tid >> 5;
    if (tid == 0) carry = 0;
    __syncthreads();
    for (int base = 0; base < n; base += 4096) {
        int i0 = base + tid * 4;
        int v[4];
#pragma unroll
        for (int k = 0; k < 4; k++) v[k] = (i0 + k < n) ? deg[i0 + k] : 0;
        int s = v[0] + v[1] + v[2] + v[3];
        int incl = s;
#pragma unroll
        for (int o = 1; o < 32; o <<= 1) {
            int tt = __shfl_up_sync(0xffffffffu, incl, o);
            if (lane >= o) incl += tt;
        }
        if (lane == 31) wsum[wid] = incl;
        __syncthreads();
        if (wid == 0) {
            int t2 = wsum[lane];
#pragma unroll
            for (int o = 1; o < 32; o <<= 1) {
                int tt = __shfl_up_sync(0xffffffffu, t2, o);
                if (lane >= o) t2 += tt;
            }
            wsum[lane] = t2;
        }
        __syncthreads();
        int woff = (wid == 0) ? 0 : wsum[wid - 1];
        int run = carry + woff + incl - s;
#pragma unroll
        for (int k = 0; k < 4; k++) {
            if (i0 + k < n) { off[i0 + k] = run; cur[i0 + k] = run; }
            run += v[k];
        }
        __syncthreads();
        if (tid == 0) carry += wsum[31];
        __syncthreads();
    }
    if (threadIdx.x == 0) off[n] = carry;
}

// ---------------- K3: scatter + posn + fused maxabs ------------------------------
__global__ void k_scat(const int* __restrict__ ei, const int* __restrict__ ei2,
                       const float* __restrict__ ea) {
    int t = blockIdx.x * blockDim.x + threadIdx.x;
    if (t < Ee) {
        int p = atomicAdd(&g_curD1[ei[Ee + t]], 1);
        float4 v;
        v.x = ea[3 * t]; v.y = ea[3 * t + 1]; v.z = ea[3 * t + 2];
        v.w = __int_as_float(ei[t]);
        g_e4[p] = v;
    }
    if (t < C1n) {
        float ic = 1.f / fmaxf((float)gz.cntc1[t], 1.f);
        float4 pn;
        pn.x = gz.possum[t * 3] * ic;
        pn.y = gz.possum[t * 3 + 1] * ic;
        pn.z = gz.possum[t * 3 + 2] * ic;
        pn.w = 0.f;
        g_posn[t] = pn;
    }
    float m = 0.f;
    if (t < E2n) {
        int s = ei2[t], d = ei2[E2n + t];
        int p = atomicAdd(&g_curD2[d], 1);
        g_csrD2s[p] = s;
        float is = 1.f / fmaxf((float)gz.cntc1[s], 1.f);
        float id = 1.f / fmaxf((float)gz.cntc1[d], 1.f);
#pragma unroll
        for (int k = 0; k < 3; k++)
            m = fmaxf(m, fabsf(gz.possum[s * 3 + k] * is - gz.possum[d * 3 + k] * id));
    }
#pragma unroll
    for (int o = 16; o; o >>= 1) m = fmaxf(m, __shfl_xor_sync(0xffffffffu, m, o));
    if ((threadIdx.x & 31) == 0 && m > 0.f) atomicMax((int*)&gz.maxabs, __float_as_int(m));
}

// ---------------- K4: conv1 edge pass -> T1 (warp per dst node, proven) ---------
__global__ void __launch_bounds__(256) k_conv1(
        const float* __restrict__ x,
        const float* __restrict__ w1a, const float* __restrict__ b1a) {
    int tid = threadIdx.x;
    int d = (blockIdx.x * blockDim.x + tid) >> 5;
    int lane = tid & 31;
    if (d >= Nn) return;
    float wa0 = 0.f, wa1 = 0.f, wa2 = 0.f, ba = 0.f;
    if (lane < 25) { wa0 = w1a[lane]; wa1 = w1a[25 + lane]; wa2 = w1a[50 + lane]; ba = b1a[lane]; }
    else if (lane == 25) ba = 1.f;   // h == 1 -> x-sum (bias) row
    float acc0 = 0.f, acc1 = 0.f, acc2 = 0.f, acc3 = 0.f, acc4 = 0.f, acc5 = 0.f;
    int p0 = g_offD1[d], p1 = g_offD1[d + 1];
    for (int p = p0; p < p1; p++) {
        float4 e4 = g_e4[p];
        int src = __float_as_int(e4.w);
        const float2* xs = (const float2*)(x + src * 6);
        float2 x01 = xs[0], x23 = xs[1], x45 = xs[2];
        float h = fmaxf(fmaf(e4.x, wa0, fmaf(e4.y, wa1, fmaf(e4.z, wa2, ba))), 0.f);
        acc0 = fmaf(h, x01.x, acc0); acc1 = fmaf(h, x01.y, acc1);
        acc2 = fmaf(h, x23.x, acc2); acc3 = fmaf(h, x23.y, acc3);
        acc4 = fmaf(h, x45.x, acc4); acc5 = fmaf(h, x45.y, acc5);
    }
    float invd = 1.f / fmaxf((float)(p1 - p0), 1.f);
    float* Trow = g_T1 + (size_t)d * T1S + lane * 6;
    if (lane < 26) {
        Trow[0] = acc0 * invd; Trow[1] = acc1 * invd; Trow[2] = acc2 * invd;
        Trow[3] = acc3 * invd; Trow[4] = acc4 * invd; Trow[5] = acc5 * invd;
    } else if (lane == 26) {
#pragma unroll
        for (int i = 0; i < 6; i++) Trow[i] = x[d * 6 + i];
    }
}

// ---------------- K5: gemm1  out = T1 @ [w1b|b1b|root1] + bias1 -> elu -> pool1 --
__global__ void __launch_bounds__(256) k_gemm1(
        const float* __restrict__ w1b, const float* __restrict__ b1b,
        const float* __restrict__ root1, const float* __restrict__ bias1,
        const int* __restrict__ cl1) {
    __shared__ __align__(16) float Ws[192 * 32];
    __shared__ __align__(16) float Ts[32 * 136];
    int tid = threadIdx.x;
    int nb = blockIdx.x * 128;
    for (int idx = tid; idx < 192 * 32; idx += 256) {
        float v = 0.f;
        if (idx < 4800)      v = w1b[idx];
        else if (idx < 4992) v = b1b[idx - 4800];
        else if (idx < 5184) v = root1[idx - 4992];
        Ws[idx] = v;
    }
    int cg = tid & 7, ng = tid >> 3;
    int c4 = cg * 4, n4 = ng * 4;
    float acc[4][4];
#pragma unroll
    for (int a = 0; a < 4; a++)
#pragma unroll
        for (int b = 0; b < 4; b++) acc[a][b] = 0.f;
    for (int kk = 0; kk < K1; kk += 32) {
        __syncthreads();
        for (int idx = tid; idx < 128 * 32; idx += 256) {
            int n = idx >> 5, k = idx & 31;
            float v = 0.f;
            if (kk + k < K1 && nb + n < Nn) v = g_T1[(size_t)(nb + n) * T1S + kk + k];
            Ts[k * 136 + n] = v;
        }
        __syncthreads();
#pragma unroll 8
        for (int k = 0; k < 32; k++) {
            float4 tv = *(const float4*)&Ts[k * 136 + n4];
            float4 wv = *(const float4*)&Ws[(kk + k) * 32 + c4];
            float ta[4] = {tv.x, tv.y, tv.z, tv.w};
            float wa[4] = {wv.x, wv.y, wv.z, wv.w};
#pragma unroll
            for (int a = 0; a < 4; a++)
#pragma unroll
                for (int b = 0; b < 4; b++) acc[a][b] = fmaf(ta[a], wa[b], acc[a][b]);
        }
    }
#pragma unroll
    for (int a = 0; a < 4; a++) {
        int n = nb + n4 + a;
        if (n >= Nn) continue;
        int c = cl1[n];
#pragma unroll
        for (int b = 0; b < 4; b++) {
            float v = elu1(acc[a][b] + bias1[c4 + b]);
            atomicMaxFloat(&gf.xp[c * 32 + c4 + b], v);
        }
    }
}

// ---------------- K6: conv2 edge pass -> T2 (warp per dst, posn float4) ----------
__global__ void __launch_bounds__(256) k_conv2(
        const float* __restrict__ w2a, const float* __restrict__ b2a) {
    int tid = threadIdx.x;
    int d = (blockIdx.x * blockDim.x + tid) >> 5;
    int lane = tid & 31;
    if (d >= C1n) return;
    float wa0 = 0.f, wa1 = 0.f, wa2 = 0.f, ba = 0.f;
    if (lane < 25) { wa0 = w2a[lane]; wa1 = w2a[25 + lane]; wa2 = w2a[50 + lane]; ba = b2a[lane]; }
    else if (lane == 25) ba = 1.f;
    float4 pdn = g_posn[d];
    float inv = 0.5f / gz.maxabs;
    float acc[26];
#pragma unroll
    for (int r = 0; r < 26; r++) acc[r] = 0.f;
    int p0 = g_offD2[d], p1 = g_offD2[d + 1];
    for (int p = p0; p < p1; p++) {
        int src = g_csrD2s[p];
        float4 ps = g_posn[src];
        float xpi = fixneg(gf.xp[src * 32 + lane]);
        float e0 = fmaf(ps.x - pdn.x, inv, 0.5f);
        float e1 = fmaf(ps.y - pdn.y, inv, 0.5f);
        float e2 = fmaf(ps.z - pdn.z, inv, 0.5f);
        float h = fmaxf(fmaf(e0, wa0, fmaf(e1, wa1, fmaf(e2, wa2, ba))), 0.f);
#pragma unroll
        for (int r = 0; r < 26; r++) {
            float hr = __shfl_sync(0xffffffffu, h, r);
            acc[r] = fmaf(hr, xpi, acc[r]);
        }
    }
    float invd = 1.f / fmaxf((float)(p1 - p0), 1.f);
    float* Trow = g_T2 + (size_t)d * T2S;
#pragma unroll
    for (int r = 0; r < 26; r++) Trow[r * 32 + lane] = acc[r] * invd;
    Trow[832 + lane] = fixneg(gf.xp[d * 32 + lane]);   // root columns
}

// ---------------- K7: gemm2, double-buffered cp.async, T kept [n][k] --------------
// 27 k-tiles of 32 (aligned with w2b|b2b|root2 splits). 64-node tile,
// thread = 4 nodes x 4 cols (cg=tid&15 -> c4, ng=tid>>4 -> n4).
__global__ void __launch_bounds__(256) k_gemm2(
        const float* __restrict__ w2b, const float* __restrict__ b2b,
        const float* __restrict__ root2, const float* __restrict__ bias2,
        const int* __restrict__ cl2) {
    __shared__ __align__(16) float Ws[2][32 * 64];   // [k][c]
    __shared__ __align__(16) float Ts[2][64 * 36];   // [n][k], pad 36
    int tid = threadIdx.x;
    int nb = blockIdx.x * 64;
    int cg = tid & 15, ng = tid >> 4;
    int c4 = cg * 4, n4 = ng * 4;

    // stage tile tt into buffer buf
    auto stage = [&](int buf, int tt) {
        const float* wsrc = (tt < 25) ? (w2b + tt * 2048) : (tt == 25 ? b2b : root2);
        int kk = tt * 32;
#pragma unroll
        for (int i = tid; i < 512; i += 256)
            cp16(smem_u32(&Ws[buf][i * 4]), wsrc + i * 4, 16);
#pragma unroll
        for (int i = tid; i < 512; i += 256) {
            int n = i >> 3, kc = (i & 7) * 4;
            const float* src = g_T2;
            int bytes = 0;
            if (nb + n < C1n) { src = g_T2 + (size_t)(nb + n) * T2S + kk + kc; bytes = 16; }
            cp16(smem_u32(&Ts[buf][n * 36 + kc]), src, bytes);
        }
        asm volatile("cp.async.commit_group;");
    };

    float acc[4][4];
#pragma unroll
    for (int a = 0; a < 4; a++)
#pragma unroll
        for (int b = 0; b < 4; b++) acc[a][b] = 0.f;

    stage(0, 0);
    for (int t = 0; t < 27; t++) {
        if (t < 26) {
            stage((t + 1) & 1, t + 1);
            asm volatile("cp.async.wait_group 1;");
        } else {
            asm volatile("cp.async.wait_group 0;");
        }
        __syncthreads();
        int buf = t & 1;
#pragma unroll
        for (int k = 0; k < 32; k += 4) {
            float4 t0 = *(const float4*)&Ts[buf][(n4 + 0) * 36 + k];
            float4 t1 = *(const float4*)&Ts[buf][(n4 + 1) * 36 + k];
            float4 t2 = *(const float4*)&Ts[buf][(n4 + 2) * 36 + k];
            float4 t3 = *(const float4*)&Ts[buf][(n4 + 3) * 36 + k];
            float4 w0 = *(const float4*)&Ws[buf][(k + 0) * 64 + c4];
            float4 w1 = *(const float4*)&Ws[buf][(k + 1) * 64 + c4];
            float4 w2 = *(const float4*)&Ws[buf][(k + 2) * 64 + c4];
            float4 w3 = *(const float4*)&Ws[buf][(k + 3) * 64 + c4];
            float ta[4][4] = {{t0.x, t0.y, t0.z, t0.w}, {t1.x, t1.y, t1.z, t1.w},
                              {t2.x, t2.y, t2.z, t2.w}, {t3.x, t3.y, t3.z, t3.w}};
            float wj[4][4] = {{w0.x, w0.y, w0.z, w0.w}, {w1.x, w1.y, w1.z, w1.w},
                              {w2.x, w2.y, w2.z, w2.w}, {w3.x, w3.y, w3.z, w3.w}};
#pragma unroll
            for (int a = 0; a < 4; a++)
#pragma unroll
                for (int j = 0; j < 4; j++)
#pragma unroll
                    for (int b = 0; b < 4; b++)
                        acc[a][b] = fmaf(ta[a][j], wj[j][b], acc[a][b]);
        }
        __syncthreads();
    }
#pragma unroll
    for (int a = 0; a < 4; a++) {
        int n = nb + n4 + a;
        if (n >= C1n) continue;
        int c2 = cl2[n];
#pragma unroll
        for (int b = 0; b < 4; b++) {
            float v = elu1(acc[a][b] + bias2[c4 + b]);
            atomicMaxFloat(&gf.x3[c2 * 64 + c4 + b], v);
        }
        if (cg == 0) atomicMax(&gf.batch2[c2], max(gf.batchp[n], 0));
    }
}

// ---------------- K8: pool2 finalize + global mean scatter ----------------------
__global__ void k_pool2() {
    int c = (blockIdx.x * blockDim.x + threadIdx.x) >> 5;
    int lane = threadIdx.x & 31;
    if (c >= C2n) return;
    float v0 = fixneg(gf.x3[c * 64 + lane]);
    float v1 = fixneg(gf.x3[c * 64 + lane + 32]);
    int b = max(gf.batch2[c], 0);
    atomicAdd(&gz.gsum[b * 64 + lane], v0);
    atomicAdd(&gz.gsum[b * 64 + lane + 32], v1);
    if (lane == 0) atomicAdd(&gz.gcnt[b], 1.f);
}

// ---------------- K9: FC head + log_softmax ------------------------------------
__global__ void k_head(const float* __restrict__ fc1w, const float* __restrict__ fc1b,
                       const float* __restrict__ fc2w, const float* __restrict__ fc2b,
                       float* __restrict__ out) {
    __shared__ float g[16 * 64];
    __shared__ float hh[16 * 128];
    __shared__ float lg[16 * 10];
    int tid = threadIdx.x;
    for (int i = tid; i < 16 * 64; i += 256) g[i] = gz.gsum[i] / fmaxf(gz.gcnt[i >> 6], 1.f);
    __syncthreads();
    for (int o = tid; o < 16 * 128; o += 256) {
        int b = o >> 7, j = o & 127;
        float acc = fc1b[j];
        for (int k = 0; k < 64; k++) acc = fmaf(g[b * 64 + k], fc1w[k * 128 + j], acc);
        hh[o] = elu1(acc);
    }
    __syncthreads();
    if (tid < 160) {
        int b = tid / 10, k = tid % 10;
        float acc = fc2b[k];
        for (int j = 0; j < 128; j++) acc = fmaf(hh[b * 128 + j], fc2w[j * 10 + k], acc);
        lg[tid] = acc;
    }
    __syncthreads();
    if (tid < 16) {
        float m = -1e30f;
        for (int k = 0; k < 10; k++) m = fmaxf(m, lg[tid * 10 + k]);
        float s = 0.f;
        for (int k = 0; k < 10; k++) s += expf(lg[tid * 10 + k] - m);
        float ls = logf(s) + m;
        for (int k = 0; k < 10; k++) out[tid * 10 + k] = lg[tid * 10 + k] - ls;
    }
}

// ---------------- host launcher --------------------------------------------------
extern "C" void kernel_launch(void* const* d_in, const int* in_sizes, int n_in,
                              void* d_out, int out_size) {
    const float *x, *ea, *pos, *w1a, *b1a, *w1b, *b1b, *root1, *bias1;
    const float *w2a, *b2a, *w2b, *b2b, *root2, *bias2, *fc1w, *fc1b, *fc2w, *fc2b;
    const int *ei, *batch, *cl1, *ei2, *cl2;

    if (in_sizes[3] == 2 * Ee) {
        x = (const float*)d_in[0];  ea = (const float*)d_in[1];  pos = (const float*)d_in[2];
        ei = (const int*)d_in[3];   batch = (const int*)d_in[4]; cl1 = (const int*)d_in[5];
        ei2 = (const int*)d_in[6];  cl2 = (const int*)d_in[7];
        w1a = (const float*)d_in[8];  b1a = (const float*)d_in[9];
        w1b = (const float*)d_in[10]; b1b = (const float*)d_in[11];
        root1 = (const float*)d_in[12]; bias1 = (const float*)d_in[13];
        w2a = (const float*)d_in[14]; b2a = (const float*)d_in[15];
        w2b = (const float*)d_in[16]; b2b = (const float*)d_in[17];
        root2 = (const float*)d_in[18]; bias2 = (const float*)d_in[19];
        fc1w = (const float*)d_in[20]; fc1b = (const float*)d_in[21];
        fc2w = (const float*)d_in[22]; fc2b = (const float*)d_in[23];
    } else {
        x = (const float*)d_in[0];  ea = (const float*)d_in[1];  pos = (const float*)d_in[2];
        w1a = (const float*)d_in[3];  b1a = (const float*)d_in[4];
        w1b = (const float*)d_in[5];  b1b = (const float*)d_in[6];
        root1 = (const float*)d_in[7]; bias1 = (const float*)d_in[8];
        w2a = (const float*)d_in[9];  b2a = (const float*)d_in[10];
        w2b = (const float*)d_in[11]; b2b = (const float*)d_in[12];
        root2 = (const float*)d_in[13]; bias2 = (const float*)d_in[14];
        fc1w = (const float*)d_in[15]; fc1b = (const float*)d_in[16];
        fc2w = (const float*)d_in[17]; fc2b = (const float*)d_in[18];
        ei = (const int*)d_in[19];  batch = (const int*)d_in[20]; cl1 = (const int*)d_in[21];
        ei2 = (const int*)d_in[22]; cl2 = (const int*)d_in[23];
    }

    void *pz = nullptr, *pf = nullptr;
    cudaGetSymbolAddress(&pz, gz);
    cudaGetSymbolAddress(&pf, gf);
    cudaMemsetAsync(pz, 0, sizeof(ZBlk));
    cudaMemsetAsync(pf, 0xff, sizeof(FBlk));

    k_hist<<<(Ee + 255) / 256, 256>>>(ei, ei2, cl1, pos, batch);
    k_scan<<<2, 1024>>>();
    k_scat<<<(Ee + 255) / 256, 256>>>(ei, ei2, ea);
    k_conv1<<<3750, 256>>>(x, w1a, b1a);
    k_gemm1<<<(Nn + 127) / 128, 256>>>(w1b, b1b, root1, bias1, cl1);
    k_conv2<<<1875, 256>>>(w2a, b2a);
    k_gemm2<<<(C1n + 63) / 64, 256>>>(w2b, b2b, root2, bias2, cl2);
    k_pool2<<<938, 256>>>();
    k_head<<<1, 256>>>(fc1w, fc1b, fc2w, fc2b, (float*)d_out);
}

// round 16
// speedup vs baseline: 1.6513x; 1.0732x over previous
#include <cuda_runtime.h>
#include <math.h>
#include <limits.h>

#define Nn 30000
#define Ee 400000
#define C1n 15000
#define E2n 100000
#define C2n 7500
#define Bn 16

#define T1S 168   // T1 row stride (162 used)
#define K1 162    // 150 w1b + 6 b1b + 6 root1
#define T2S 864   // T2 row stride
#define K2 864    // 800 w2b + 32 b2b + 32 root2

typedef unsigned long long ull;

// ---------------- zero-init block (single memset 0) ---------------------------
struct ZBlk {
    int   degD1[Nn];
    int   degD2[C1n], cntc1[C1n];
    float possum[C1n * 3];
    float gsum[Bn * 64];
    float gcnt[Bn];
    float maxabs;
};
// ---------------- 0xff-init block (single memset 0xff) ------------------------
struct FBlk {
    float xp[C1n * 32];      // 0xffffffff sentinel (loses to all atomicMaxFloat)
    float x3[C2n * 64];
    int   batchp[C1n];       // -1
    int   batch2[C2n];       // -1
};
__device__ ZBlk gz;
__device__ FBlk gf;

// ---------------- uninitialized scratch ----------------------------------------
__device__ int g_offD1[Nn + 1], g_curD1[Nn];
__device__ int g_offD2[C1n + 1], g_curD2[C1n];
__device__ __align__(16) float4 g_e4[Ee];          // {ea0,ea1,ea2, src-bits} dst-sorted
__device__ int g_csrD2s[E2n];                      // src ids dst-sorted
__device__ __align__(16) float4 g_posn[C1n];       // normalized cluster positions
__device__ __align__(16) float g_T1[(size_t)Nn * T1S];
__device__ __align__(16) float g_T2[(size_t)C1n * T2S];

__device__ __forceinline__ void atomicMaxFloat(float* addr, float val) {
    if (val >= 0.f) atomicMax((int*)addr, __float_as_int(val));
    else            atomicMin((unsigned int*)addr, __float_as_uint(val));
}
__device__ __forceinline__ float elu1(float v) { return v > 0.f ? v : expm1f(v); }
__device__ __forceinline__ float fixneg(float v) { return (v > -3e38f) ? v : 0.f; }

__device__ __forceinline__ unsigned smem_u32(const void* p) {
    return (unsigned)__cvta_generic_to_shared(p);
}
__device__ __forceinline__ void cp16(unsigned dst, const void* src, int bytes) {
    asm volatile("cp.async.cg.shared.global [%0], [%1], 16, %2;"
                 :: "r"(dst), "l"(src), "r"(bytes));
}

// ---------------- K1: histograms + pool-input scatters --------------------------
__global__ void k_hist(const int* __restrict__ ei, const int* __restrict__ ei2,
                       const int* __restrict__ cl1, const float* __restrict__ pos,
                       const int* __restrict__ batch) {
    int t = blockIdx.x * blockDim.x + threadIdx.x;
    if (t < Ee)  atomicAdd(&gz.degD1[ei[Ee + t]], 1);
    if (t < E2n) atomicAdd(&gz.degD2[ei2[E2n + t]], 1);
    if (t < Nn) {
        int c = cl1[t];
        atomicAdd(&gz.cntc1[c], 1);
        atomicAdd(&gz.possum[c * 3],     pos[t * 3]);
        atomicAdd(&gz.possum[c * 3 + 1], pos[t * 3 + 1]);
        atomicAdd(&gz.possum[c * 3 + 2], pos[t * 3 + 2]);
        atomicMax(&gf.batchp[c], batch[t]);
    }
}

// ---------------- K2: exclusive scans (2 arrays, 4 elems/thread) ----------------
__global__ void k_scan() {
    const int* deg; int* off; int* cur; int n;
    if (blockIdx.x == 0) { deg = gz.degD1; off = g_offD1; cur = g_curD1; n = Nn; }
    else                 { deg = gz.degD2; off = g_offD2; cur = g_curD2; n = C1n; }
    __shared__ int wsum[32];
    __shared__ int carry;
    int tid = threadIdx.x, lane = tid & 31, wid = tid >> 5;
    if (tid == 0) carry = 0;
    __syncthreads();
    for (int base = 0; base < n; base += 4096) {
        int i0 = base + tid * 4;
        int v[4];
#pragma unroll
        for (int k = 0; k < 4; k++) v[k] = (i0 + k < n) ? deg[i0 + k] : 0;
        int s = v[0] + v[1] + v[2] + v[3];
        int incl = s;
#pragma unroll
        for (int o = 1; o < 32; o <<= 1) {
            int tt = __shfl_up_sync(0xffffffffu, incl, o);
            if (lane >= o) incl += tt;
        }
        if (lane == 31) wsum[wid] = incl;
        __syncthreads();
        if (wid == 0) {
            int t2 = wsum[lane];
#pragma unroll
            for (int o = 1; o < 32; o <<= 1) {
                int tt = __shfl_up_sync(0xffffffffu, t2, o);
                if (lane >= o) t2 += tt;
            }
            wsum[lane] = t2;
        }
        __syncthreads();
        int woff = (wid == 0) ? 0 : wsum[wid - 1];
        int run = carry + woff + incl - s;
#pragma unroll
        for (int k = 0; k < 4; k++) {
            if (i0 + k < n) { off[i0 + k] = run; cur[i0 + k] = run; }
            run += v[k];
        }
        __syncthreads();
        if (tid == 0) carry += wsum[31];
        __syncthreads();
    }
    if (threadIdx.x == 0) off[n] = carry;
}

// ---------------- K3: scatter + posn + fused maxabs ------------------------------
__global__ void k_scat(const int* __restrict__ ei, const int* __restrict__ ei2,
                       const float* __restrict__ ea) {
    int t = blockIdx.x * blockDim.x + threadIdx.x;
    if (t < Ee) {
        int p = atomicAdd(&g_curD1[ei[Ee + t]], 1);
        float4 v;
        v.x = ea[3 * t]; v.y = ea[3 * t + 1]; v.z = ea[3 * t + 2];
        v.w = __int_as_float(ei[t]);
        g_e4[p] = v;
    }
    if (t < C1n) {
        float ic = 1.f / fmaxf((float)gz.cntc1[t], 1.f);
        float4 pn;
        pn.x = gz.possum[t * 3] * ic;
        pn.y = gz.possum[t * 3 + 1] * ic;
        pn.z = gz.possum[t * 3 + 2] * ic;
        pn.w = 0.f;
        g_posn[t] = pn;
    }
    float m = 0.f;
    if (t < E2n) {
        int s = ei2[t], d = ei2[E2n + t];
        int p = atomicAdd(&g_curD2[d], 1);
        g_csrD2s[p] = s;
        float is = 1.f / fmaxf((float)gz.cntc1[s], 1.f);
        float id = 1.f / fmaxf((float)gz.cntc1[d], 1.f);
#pragma unroll
        for (int k = 0; k < 3; k++)
            m = fmaxf(m, fabsf(gz.possum[s * 3 + k] * is - gz.possum[d * 3 + k] * id));
    }
#pragma unroll
    for (int o = 16; o; o >>= 1) m = fmaxf(m, __shfl_xor_sync(0xffffffffu, m, o));
    if ((threadIdx.x & 31) == 0 && m > 0.f) atomicMax((int*)&gz.maxabs, __float_as_int(m));
}

// ---------------- K4: conv1 edge pass -> T1 (warp per dst node, proven) ---------
__global__ void __launch_bounds__(256) k_conv1(
        const float* __restrict__ x,
        const float* __restrict__ w1a, const float* __restrict__ b1a) {
    int tid = threadIdx.x;
    int d = (blockIdx.x * blockDim.x + tid) >> 5;
    int lane = tid & 31;
    if (d >= Nn) return;
    float wa0 = 0.f, wa1 = 0.f, wa2 = 0.f, ba = 0.f;
    if (lane < 25) { wa0 = w1a[lane]; wa1 = w1a[25 + lane]; wa2 = w1a[50 + lane]; ba = b1a[lane]; }
    else if (lane == 25) ba = 1.f;   // h == 1 -> x-sum (bias) row
    float acc0 = 0.f, acc1 = 0.f, acc2 = 0.f, acc3 = 0.f, acc4 = 0.f, acc5 = 0.f;
    int p0 = g_offD1[d], p1 = g_offD1[d + 1];
    for (int p = p0; p < p1; p++) {
        float4 e4 = g_e4[p];
        int src = __float_as_int(e4.w);
        const float2* xs = (const float2*)(x + src * 6);
        float2 x01 = xs[0], x23 = xs[1], x45 = xs[2];
        float h = fmaxf(fmaf(e4.x, wa0, fmaf(e4.y, wa1, fmaf(e4.z, wa2, ba))), 0.f);
        acc0 = fmaf(h, x01.x, acc0); acc1 = fmaf(h, x01.y, acc1);
        acc2 = fmaf(h, x23.x, acc2); acc3 = fmaf(h, x23.y, acc3);
        acc4 = fmaf(h, x45.x, acc4); acc5 = fmaf(h, x45.y, acc5);
    }
    float invd = 1.f / fmaxf((float)(p1 - p0), 1.f);
    float* Trow = g_T1 + (size_t)d * T1S + lane * 6;
    if (lane < 26) {
        Trow[0] = acc0 * invd; Trow[1] = acc1 * invd; Trow[2] = acc2 * invd;
        Trow[3] = acc3 * invd; Trow[4] = acc4 * invd; Trow[5] = acc5 * invd;
    } else if (lane == 26) {
#pragma unroll
        for (int i = 0; i < 6; i++) Trow[i] = x[d * 6 + i];
    }
}

// ---------------- K5: gemm1, double-buffered cp.async ----------------------------
// 6 k-tiles of 32 over concat [w1b|b1b|root1] (5184 floats, chunk-aligned splits).
// 128-node tile, thread = 4 nodes x 4 cols (cg=tid&7, ng=tid>>3).
__global__ void __launch_bounds__(256) k_gemm1(
        const float* __restrict__ w1b, const float* __restrict__ b1b,
        const float* __restrict__ root1, const float* __restrict__ bias1,
        const int* __restrict__ cl1) {
    __shared__ __align__(16) float Ws[2][32 * 32];    // [k][c]
    __shared__ __align__(16) float Ts[2][128 * 36];   // [n][k], pad 36
    int tid = threadIdx.x;
    int nb = blockIdx.x * 128;
    int cg = tid & 7, ng = tid >> 3;
    int c4 = cg * 4, n4 = ng * 4;

    auto stage = [&](int buf, int t) {
        // W: concat element range [1024t, 1024(t+1)); one 16B chunk per thread
        {
            int e = t * 1024 + tid * 4;
            const float* src = w1b;
            int bytes = 16;
            if (e < 4800)       src = w1b + e;
            else if (e < 4992)  src = b1b + (e - 4800);
            else if (e < 5184)  src = root1 + (e - 4992);
            else bytes = 0;
            cp16(smem_u32(&Ws[buf][tid * 4]), src, bytes);
        }
        // T: 128 rows x 8 chunks, zfill past K1 and OOB nodes
        int kk = t * 32;
#pragma unroll
        for (int i = tid; i < 1024; i += 256) {
            int n = i >> 3, kc = (i & 7) * 4;
            int k = kk + kc;
            const float* src = g_T1;
            int bytes = 0;
            if (nb + n < Nn && k < K1) {
                src = g_T1 + (size_t)(nb + n) * T1S + k;
                bytes = min(16, (K1 - k) * 4);
            }
            cp16(smem_u32(&Ts[buf][n * 36 + kc]), src, bytes);
        }
        asm volatile("cp.async.commit_group;");
    };

    float acc[4][4];
#pragma unroll
    for (int a = 0; a < 4; a++)
#pragma unroll
        for (int b = 0; b < 4; b++) acc[a][b] = 0.f;

    stage(0, 0);
    for (int t = 0; t < 6; t++) {
        if (t < 5) {
            stage((t + 1) & 1, t + 1);
            asm volatile("cp.async.wait_group 1;");
        } else {
            asm volatile("cp.async.wait_group 0;");
        }
        __syncthreads();
        int buf = t & 1;
#pragma unroll
        for (int k = 0; k < 32; k += 4) {
            float4 t0 = *(const float4*)&Ts[buf][(n4 + 0) * 36 + k];
            float4 t1 = *(const float4*)&Ts[buf][(n4 + 1) * 36 + k];
            float4 t2 = *(const float4*)&Ts[buf][(n4 + 2) * 36 + k];
            float4 t3 = *(const float4*)&Ts[buf][(n4 + 3) * 36 + k];
            float4 w0 = *(const float4*)&Ws[buf][(k + 0) * 32 + c4];
            float4 w1 = *(const float4*)&Ws[buf][(k + 1) * 32 + c4];
            float4 w2 = *(const float4*)&Ws[buf][(k + 2) * 32 + c4];
            float4 w3 = *(const float4*)&Ws[buf][(k + 3) * 32 + c4];
            float ta[4][4] = {{t0.x, t0.y, t0.z, t0.w}, {t1.x, t1.y, t1.z, t1.w},
                              {t2.x, t2.y, t2.z, t2.w}, {t3.x, t3.y, t3.z, t3.w}};
            float wj[4][4] = {{w0.x, w0.y, w0.z, w0.w}, {w1.x, w1.y, w1.z, w1.w},
                              {w2.x, w2.y, w2.z, w2.w}, {w3.x, w3.y, w3.z, w3.w}};
#pragma unroll
            for (int a = 0; a < 4; a++)
#pragma unroll
                for (int j = 0; j < 4; j++)
#pragma unroll
                    for (int b = 0; b < 4; b++)
                        acc[a][b] = fmaf(ta[a][j], wj[j][b], acc[a][b]);
        }
        __syncthreads();
    }
#pragma unroll
    for (int a = 0; a < 4; a++) {
        int n = nb + n4 + a;
        if (n >= Nn) continue;
        int c = cl1[n];
#pragma unroll
        for (int b = 0; b < 4; b++) {
            float v = elu1(acc[a][b] + bias1[c4 + b]);
            atomicMaxFloat(&gf.xp[c * 32 + c4 + b], v);
        }
    }
}

// ---------------- K6: conv2 edge pass -> T2 (warp per dst, posn float4) ----------
__global__ void __launch_bounds__(256) k_conv2(
        const float* __restrict__ w2a, const float* __restrict__ b2a) {
    int tid = threadIdx.x;
    int d = (blockIdx.x * blockDim.x + tid) >> 5;
    int lane = tid & 31;
    if (d >= C1n) return;
    float wa0 = 0.f, wa1 = 0.f, wa2 = 0.f, ba = 0.f;
    if (lane < 25) { wa0 = w2a[lane]; wa1 = w2a[25 + lane]; wa2 = w2a[50 + lane]; ba = b2a[lane]; }
    else if (lane == 25) ba = 1.f;
    float4 pdn = g_posn[d];
    float inv = 0.5f / gz.maxabs;
    float acc[26];
#pragma unroll
    for (int r = 0; r < 26; r++) acc[r] = 0.f;
    int p0 = g_offD2[d], p1 = g_offD2[d + 1];
    for (int p = p0; p < p1; p++) {
        int src = g_csrD2s[p];
        float4 ps = g_posn[src];
        float xpi = fixneg(gf.xp[src * 32 + lane]);
        float e0 = fmaf(ps.x - pdn.x, inv, 0.5f);
        float e1 = fmaf(ps.y - pdn.y, inv, 0.5f);
        float e2 = fmaf(ps.z - pdn.z, inv, 0.5f);
        float h = fmaxf(fmaf(e0, wa0, fmaf(e1, wa1, fmaf(e2, wa2, ba))), 0.f);
#pragma unroll
        for (int r = 0; r < 26; r++) {
            float hr = __shfl_sync(0xffffffffu, h, r);
            acc[r] = fmaf(hr, xpi, acc[r]);
        }
    }
    float invd = 1.f / fmaxf((float)(p1 - p0), 1.f);
    float* Trow = g_T2 + (size_t)d * T2S;
#pragma unroll
    for (int r = 0; r < 26; r++) Trow[r * 32 + lane] = acc[r] * invd;
    Trow[832 + lane] = fixneg(gf.xp[d * 32 + lane]);   // root columns
}

// ---------------- K7: gemm2, double-buffered cp.async (R15-proven) ---------------
__global__ void __launch_bounds__(256) k_gemm2(
        const float* __restrict__ w2b, const float* __restrict__ b2b,
        const float* __restrict__ root2, const float* __restrict__ bias2,
        const int* __restrict__ cl2) {
    __shared__ __align__(16) float Ws[2][32 * 64];   // [k][c]
    __shared__ __align__(16) float Ts[2][64 * 36];   // [n][k], pad 36
    int tid = threadIdx.x;
    int nb = blockIdx.x * 64;
    int cg = tid & 15, ng = tid >> 4;
    int c4 = cg * 4, n4 = ng * 4;

    auto stage = [&](int buf, int tt) {
        const float* wsrc = (tt < 25) ? (w2b + tt * 2048) : (tt == 25 ? b2b : root2);
        int kk = tt * 32;
#pragma unroll
        for (int i = tid; i < 512; i += 256)
            cp16(smem_u32(&Ws[buf][i * 4]), wsrc + i * 4, 16);
#pragma unroll
        for (int i = tid; i < 512; i += 256) {
            int n = i >> 3, kc = (i & 7) * 4;
            const float* src = g_T2;
            int bytes = 0;
            if (nb + n < C1n) { src = g_T2 + (size_t)(nb + n) * T2S + kk + kc; bytes = 16; }
            cp16(smem_u32(&Ts[buf][n * 36 + kc]), src, bytes);
        }
        asm volatile("cp.async.commit_group;");
    };

    float acc[4][4];
#pragma unroll
    for (int a = 0; a < 4; a++)
#pragma unroll
        for (int b = 0; b < 4; b++) acc[a][b] = 0.f;

    stage(0, 0);
    for (int t = 0; t < 27; t++) {
        if (t < 26) {
            stage((t + 1) & 1, t + 1);
            asm volatile("cp.async.wait_group 1;");
        } else {
            asm volatile("cp.async.wait_group 0;");
        }
        __syncthreads();
        int buf = t & 1;
#pragma unroll
        for (int k = 0; k < 32; k += 4) {
            float4 t0 = *(const float4*)&Ts[buf][(n4 + 0) * 36 + k];
            float4 t1 = *(const float4*)&Ts[buf][(n4 + 1) * 36 + k];
            float4 t2 = *(const float4*)&Ts[buf][(n4 + 2) * 36 + k];
            float4 t3 = *(const float4*)&Ts[buf][(n4 + 3) * 36 + k];
            float4 w0 = *(const float4*)&Ws[buf][(k + 0) * 64 + c4];
            float4 w1 = *(const float4*)&Ws[buf][(k + 1) * 64 + c4];
            float4 w2 = *(const float4*)&Ws[buf][(k + 2) * 64 + c4];
            float4 w3 = *(const float4*)&Ws[buf][(k + 3) * 64 + c4];
            float ta[4][4] = {{t0.x, t0.y, t0.z, t0.w}, {t1.x, t1.y, t1.z, t1.w},
                              {t2.x, t2.y, t2.z, t2.w}, {t3.x, t3.y, t3.z, t3.w}};
            float wj[4][4] = {{w0.x, w0.y, w0.z, w0.w}, {w1.x, w1.y, w1.z, w1.w},
                              {w2.x, w2.y, w2.z, w2.w}, {w3.x, w3.y, w3.z, w3.w}};
#pragma unroll
            for (int a = 0; a < 4; a++)
#pragma unroll
                for (int j = 0; j < 4; j++)
#pragma unroll
                    for (int b = 0; b < 4; b++)
                        acc[a][b] = fmaf(ta[a][j], wj[j][b], acc[a][b]);
        }
        __syncthreads();
    }
#pragma unroll
    for (int a = 0; a < 4; a++) {
        int n = nb + n4 + a;
        if (n >= C1n) continue;
        int c2 = cl2[n];
#pragma unroll
        for (int b = 0; b < 4; b++) {
            float v = elu1(acc[a][b] + bias2[c4 + b]);
            atomicMaxFloat(&gf.x3[c2 * 64 + c4 + b], v);
        }
        if (cg == 0) atomicMax(&gf.batch2[c2], max(gf.batchp[n], 0));
    }
}

// ---------------- K8: pool2 finalize + global mean scatter ----------------------
__global__ void k_pool2() {
    int c = (blockIdx.x * blockDim.x + threadIdx.x) >> 5;
    int lane = threadIdx.x & 31;
    if (c >= C2n) return;
    float v0 = fixneg(gf.x3[c * 64 + lane]);
    float v1 = fixneg(gf.x3[c * 64 + lane + 32]);
    int b = max(gf.batch2[c], 0);
    atomicAdd(&gz.gsum[b * 64 + lane], v0);
    atomicAdd(&gz.gsum[b * 64 + lane + 32], v1);
    if (lane == 0) atomicAdd(&gz.gcnt[b], 1.f);
}

// ---------------- K9: FC head + log_softmax ------------------------------------
__global__ void k_head(const float* __restrict__ fc1w, const float* __restrict__ fc1b,
                       const float* __restrict__ fc2w, const float* __restrict__ fc2b,
                       float* __restrict__ out) {
    __shared__ float g[16 * 64];
    __shared__ float hh[16 * 128];
    __shared__ float lg[16 * 10];
    int tid = threadIdx.x;
    for (int i = tid; i < 16 * 64; i += 256) g[i] = gz.gsum[i] / fmaxf(gz.gcnt[i >> 6], 1.f);
    __syncthreads();
    for (int o = tid; o < 16 * 128; o += 256) {
        int b = o >> 7, j = o & 127;
        float acc = fc1b[j];
        for (int k = 0; k < 64; k++) acc = fmaf(g[b * 64 + k], fc1w[k * 128 + j], acc);
        hh[o] = elu1(acc);
    }
    __syncthreads();
    if (tid < 160) {
        int b = tid / 10, k = tid % 10;
        float acc = fc2b[k];
        for (int j = 0; j < 128; j++) acc = fmaf(hh[b * 128 + j], fc2w[j * 10 + k], acc);
        lg[tid] = acc;
    }
    __syncthreads();
    if (tid < 16) {
        float m = -1e30f;
        for (int k = 0; k < 10; k++) m = fmaxf(m, lg[tid * 10 + k]);
        float s = 0.f;
        for (int k = 0; k < 10; k++) s += expf(lg[tid * 10 + k] - m);
        float ls = logf(s) + m;
        for (int k = 0; k < 10; k++) out[tid * 10 + k] = lg[tid * 10 + k] - ls;
    }
}

// ---------------- host launcher --------------------------------------------------
extern "C" void kernel_launch(void* const* d_in, const int* in_sizes, int n_in,
                              void* d_out, int out_size) {
    const float *x, *ea, *pos, *w1a, *b1a, *w1b, *b1b, *root1, *bias1;
    const float *w2a, *b2a, *w2b, *b2b, *root2, *bias2, *fc1w, *fc1b, *fc2w, *fc2b;
    const int *ei, *batch, *cl1, *ei2, *cl2;

    if (in_sizes[3] == 2 * Ee) {
        x = (const float*)d_in[0];  ea = (const float*)d_in[1];  pos = (const float*)d_in[2];
        ei = (const int*)d_in[3];   batch = (const int*)d_in[4]; cl1 = (const int*)d_in[5];
        ei2 = (const int*)d_in[6];  cl2 = (const int*)d_in[7];
        w1a = (const float*)d_in[8];  b1a = (const float*)d_in[9];
        w1b = (const float*)d_in[10]; b1b = (const float*)d_in[11];
        root1 = (const float*)d_in[12]; bias1 = (const float*)d_in[13];
        w2a = (const float*)d_in[14]; b2a = (const float*)d_in[15];
        w2b = (const float*)d_in[16]; b2b = (const float*)d_in[17];
        root2 = (const float*)d_in[18]; bias2 = (const float*)d_in[19];
        fc1w = (const float*)d_in[20]; fc1b = (const float*)d_in[21];
        fc2w = (const float*)d_in[22]; fc2b = (const float*)d_in[23];
    } else {
        x = (const float*)d_in[0];  ea = (const float*)d_in[1];  pos = (const float*)d_in[2];
        w1a = (const float*)d_in[3];  b1a = (const float*)d_in[4];
        w1b = (const float*)d_in[5];  b1b = (const float*)d_in[6];
        root1 = (const float*)d_in[7]; bias1 = (const float*)d_in[8];
        w2a = (const float*)d_in[9];  b2a = (const float*)d_in[10];
        w2b = (const float*)d_in[11]; b2b = (const float*)d_in[12];
        root2 = (const float*)d_in[13]; bias2 = (const float*)d_in[14];
        fc1w = (const float*)d_in[15]; fc1b = (const float*)d_in[16];
        fc2w = (const float*)d_in[17]; fc2b = (const float*)d_in[18];
        ei = (const int*)d_in[19];  batch = (const int*)d_in[20]; cl1 = (const int*)d_in[21];
        ei2 = (const int*)d_in[22]; cl2 = (const int*)d_in[23];
    }

    void *pz = nullptr, *pf = nullptr;
    cudaGetSymbolAddress(&pz, gz);
    cudaGetSymbolAddress(&pf, gf);
    cudaMemsetAsync(pz, 0, sizeof(ZBlk));
    cudaMemsetAsync(pf, 0xff, sizeof(FBlk));

    k_hist<<<(Ee + 255) / 256, 256>>>(ei, ei2, cl1, pos, batch);
    k_scan<<<2, 1024>>>();
    k_scat<<<(Ee + 255) / 256, 256>>>(ei, ei2, ea);
    k_conv1<<<3750, 256>>>(x, w1a, b1a);
    k_gemm1<<<(Nn + 127) / 128, 256>>>(w1b, b1b, root1, bias1, cl1);
    k_conv2<<<1875, 256>>>(w2a, b2a);
    k_gemm2<<<(C1n + 63) / 64, 256>>>(w2b, b2b, root2, bias2, cl2);
    k_pool2<<<938, 256>>>();
    k_head<<<1, 256>>>(fc1w, fc1b, fc2w, fc2b, (float*)d_out);
}